// round 17
// baseline (speedup 1.0000x reference)
#include <cuda_runtime.h>
#include <cuda.h>
#include <math.h>
#include <stdint.h>

// BuildingModule: 3-state RC thermal scan, B=8192 chains x 1023 serial steps.
// 64-thread blocks = 2 independent warps (32 chains each) on SMSP0/SMSP1.
// All gmem<->smem traffic via TMA tensor bulk copies (few LARGE commands,
// issued by one lane) to unload the per-SM LSU:
//   u:   4x 2D TMA tile loads per chunk (32fl x 32 chains, SW128) -> 3-slot ring
//   out: 1x 2D TMA tile store per chunk (48fl x 32 chains) from compact ob
// Math: f32x2-packed states (0,2) + scalar state 1, incremental reciprocal
// (cubic poly for 2^-m), kl-prefolded coefficients.

#define BATCH   8192
#define TSTEPS  1024
#define CHUNK   16
#define NCHUNK  (TSTEPS / CHUNK)        // 64
#define USTRIDE (TSTEPS * 8)            // floats per chain in u
#define OSTRIDE (TSTEPS * 3)            // floats per chain in out

#define USLOT_BYTES (32 * 512)          // one u ring slot: 32 chains x 512B
#define OBUF_WORDS  (32 * 48)           // one out buffer: 32 chains x 48fl
#define OBUF_BYTES  (OBUF_WORDS * 4)    // 6144
#define WARP_BYTES  (3 * USLOT_BYTES + 2 * OBUF_BYTES)   // 61440
#define SMEM_BYTES  (2 * WARP_BYTES + 64)                // + mbarriers

typedef unsigned long long u64;

__device__ __forceinline__ float rcpa(float x) {
    float y; asm("rcp.approx.ftz.f32 %0, %1;" : "=f"(y) : "f"(x)); return y;
}
__device__ __forceinline__ float ex2a(float x) {
    float y; asm("ex2.approx.ftz.f32 %0, %1;" : "=f"(y) : "f"(x)); return y;
}
__device__ __forceinline__ u64 pk(float lo, float hi) {
    u64 r; asm("mov.b64 %0, {%1, %2};" : "=l"(r) : "f"(lo), "f"(hi)); return r;
}
__device__ __forceinline__ void upk(float& lo, float& hi, u64 v) {
    asm("mov.b64 {%0, %1}, %2;" : "=f"(lo), "=f"(hi) : "l"(v));
}
__device__ __forceinline__ u64 fma2(u64 a, u64 b, u64 c) {
    u64 r; asm("fma.rn.f32x2 %0, %1, %2, %3;" : "=l"(r) : "l"(a), "l"(b), "l"(c));
    return r;
}
__device__ __forceinline__ u64 mul2(u64 a, u64 b) {
    u64 r; asm("mul.rn.f32x2 %0, %1, %2;" : "=l"(r) : "l"(a), "l"(b)); return r;
}
__device__ __forceinline__ float4 lds128(uint32_t a) {
    float4 v;
    asm volatile("ld.shared.v4.f32 {%0,%1,%2,%3}, [%4];"
                 : "=f"(v.x), "=f"(v.y), "=f"(v.z), "=f"(v.w) : "r"(a));
    return v;
}
__device__ __forceinline__ void mbar_init(uint32_t a, uint32_t cnt) {
    asm volatile("mbarrier.init.shared.b64 [%0], %1;" :: "r"(a), "r"(cnt) : "memory");
}
__device__ __forceinline__ void mbar_expect(uint32_t a, uint32_t tx) {
    asm volatile("mbarrier.arrive.expect_tx.shared.b64 _, [%0], %1;"
                 :: "r"(a), "r"(tx) : "memory");
}
__device__ __forceinline__ void mbar_wait(uint32_t a, uint32_t parity) {
    asm volatile(
        "{\n\t.reg .pred P;\n\t"
        "WL_%=:\n\t"
        "mbarrier.try_wait.parity.acquire.cta.shared::cta.b64 P, [%0], %1, 0x989680;\n\t"
        "@P bra.uni WD_%=;\n\t"
        "bra.uni WL_%=;\n\t"
        "WD_%=:\n\t}" :: "r"(a), "r"(parity) : "memory");
}
__device__ __forceinline__ void tma_ld2d(uint32_t sdst, const CUtensorMap* tm,
                                         int x, int y, uint32_t mbar) {
    asm volatile("cp.async.bulk.tensor.2d.shared::cta.global.tile.mbarrier::complete_tx::bytes "
                 "[%0], [%1, {%2, %3}], [%4];"
                 :: "r"(sdst), "l"(tm), "r"(x), "r"(y), "r"(mbar) : "memory");
}
__device__ __forceinline__ void tma_st2d(const CUtensorMap* tm, int x, int y,
                                         uint32_t ssrc) {
    asm volatile("cp.async.bulk.tensor.2d.global.shared::cta.tile.bulk_group "
                 "[%0, {%1, %2}], [%3];"
                 :: "l"(tm), "r"(x), "r"(y), "r"(ssrc) : "memory");
}
__device__ __forceinline__ void tma_commit() {
    asm volatile("cp.async.bulk.commit_group;" ::: "memory");
}
__device__ __forceinline__ void tma_wait_read1() {
    asm volatile("cp.async.bulk.wait_group.read 1;" ::: "memory");
}
__device__ __forceinline__ void tma_wait0() {
    asm volatile("cp.async.bulk.wait_group 0;" ::: "memory");
}
__device__ __forceinline__ void fence_async() {
    asm volatile("fence.proxy.async.shared::cta;" ::: "memory");
}

extern __shared__ float smem[];

__global__ void __launch_bounds__(64)
bm_kernel(const float* __restrict__ x0g,
          const float* __restrict__ lamg,
          const __grid_constant__ CUtensorMap um,
          const __grid_constant__ CUtensorMap om)
{
    const int tid  = threadIdx.x;
    const int lane = tid & 31;
    const int wid  = tid >> 5;                 // 0 or 1 -> SMSP 0 / 1
    const int b0   = blockIdx.x * 64 + wid * 32;
    const int b    = b0 + lane;

    const uint32_t smemS = (uint32_t)__cvta_generic_to_shared(smem);
    const uint32_t ubS = smemS + wid * WARP_BYTES;            // 3 u slots
    const uint32_t obS = ubS + 3 * USLOT_BYTES;               // 2 ob buffers
    const uint32_t mb  = smemS + 2 * WARP_BYTES + wid * 24;   // 3 mbars x 8B
    float* obf = smem + (wid * WARP_BYTES + 3 * USLOT_BYTES) / 4;

    const float e12 = expf(lamg[0]);
    const float e23 = expf(lamg[1]);
    const float ee0 = expf(lamg[2]),  ee1 = expf(lamg[3]),  ee2 = expf(lamg[4]);
    const float es0 = expf(lamg[5]),  es1 = expf(lamg[6]),  es2 = expf(lamg[7]);
    const float eh0 = expf(lamg[8]),  eh1 = expf(lamg[9]),  eh2 = expf(lamg[10]);
    const float ec0 = expf(lamg[11]), ec1 = expf(lamg[12]), ec2 = expf(lamg[13]);

    const float kl0 = (float)(60.0 / 10665991.0 * 1.4426950408889634);
    const float kl1 = (float)(60.0 / 27000000.0 * 1.4426950408889634);
    const float kl2 = (float)(60.0 /  7953253.0 * 1.4426950408889634);

    const float ng12_1 = -kl1 * e12;
    const float g23_1  =  kl1 * e23;
    const float eeK1 = kl1*ee1, neeK1 = -eeK1;
    const float esK1 = kl1*es1, ehK1 = kl1*eh1, ecK1 = kl1*ec1;

    const u64 G02    = pk( kl0 * e12, -kl2 * e23);
    const u64 eeK02  = pk( kl0*ee0,  kl2*ee2);
    const u64 neeK02 = pk(-kl0*ee0, -kl2*ee2);
    const u64 esK02  = pk( kl0*es0,  kl2*es2);
    const u64 ehK02  = pk( kl0*eh0,  kl2*eh2);
    const u64 ecK02  = pk( kl0*ec0,  kl2*ec2);
    const u64 P3P3   = pk(-0.05550410866f, -0.05550410866f);
    const u64 P2P2   = pk( 0.24022650696f,  0.24022650696f);
    const u64 P1P1   = pk(-0.69314718056f, -0.69314718056f);
    const u64 ONE2   = pk(1.0f, 1.0f);

    float x0 = x0g[b * 3 + 0];
    float x1 = x0g[b * 3 + 1];
    float x2 = x0g[b * 3 + 2];
    float i0 = rcpa(x0), i1 = rcpa(x1), i2 = rcpa(x2);
    i0 = i0 * (2.0f - x0 * i0);
    i1 = i1 * (2.0f - x1 * i1);
    i2 = i2 * (2.0f - x2 * i2);

    u64 X02 = pk(x0, x2);
    u64 I02 = pk(i0, i2);

    // mbarrier init (count=1: single-lane expect_tx per stage)
    if (lane == 0) {
        mbar_init(mb + 0, 1);
        mbar_init(mb + 8, 1);
        mbar_init(mb + 16, 1);
        fence_async();
    }
    __syncwarp();

    // prime 3-deep ring: slots 0..2 <- chunks 0..2 (4 tile loads each)
    if (lane == 0) {
#pragma unroll
        for (int s = 0; s < 3; s++) {
            mbar_expect(mb + s * 8, USLOT_BYTES);
#pragma unroll
            for (int k = 0; k < 4; k++)
                tma_ld2d(ubS + s * USLOT_BYTES + k * 4096, &um,
                         s * 128 + k * 32, b0, mb + s * 8);
        }
    }

    const uint32_t sx   = (uint32_t)(lane & 7) * 16;   // swizzle xor term
    const uint32_t rub  = lane * 128;                  // row base within slot

    for (int c = 0; c < NCHUNK; c++) {
        const int s      = c % 3;
        const int parity = (c / 3) & 1;
        const int bo     = c & 1;

        mbar_wait(mb + s * 8, (uint32_t)parity);

        const uint32_t slot = ubS + s * USLOT_BYTES + rub;
        float* orow = obf + bo * OBUF_WORDS + lane * 48;

        float sb[12];

        // one-step-ahead register prefetch of the u row (swizzled LDS.128 x2)
        // unit m of row: tile (m>>3)*4096, col ((m&7)*16)^sx
        float4 ua = lds128(slot + 0 * 4096 + ((0 * 16) ^ sx));
        float4 uc = lds128(slot + 0 * 4096 + ((1 * 16) ^ sx));

#pragma unroll
        for (int j = 0; j < CHUNK; j++) {
            float4 na, nc;
            if (j < CHUNK - 1) {
                const int m0u = 2 * (j + 1);
                const uint32_t t = (uint32_t)(m0u >> 3) * 4096;
                na = lds128(slot + t + ((((uint32_t)(m0u & 7)) * 16) ^ sx));
                nc = lds128(slot + t + ((((uint32_t)((m0u + 1) & 7)) * 16) ^ sx));
            }

            // out row 16c+j <- current state, masked by u0 of this row
            {
                const bool nm = (c == 0) && (j == 0);
                const bool mv = !nm && (ua.x < 1e-6f);
                const int  st = (j & 3) * 3;
                sb[st + 0] = mv ? -1.0f : x0;
                sb[st + 1] = mv ? -1.0f : x1;
                sb[st + 2] = mv ? -1.0f : x2;
            }

            // ---- scan step: states (0,2) packed f32x2, state 1 scalar ----
            const u64 H02 = pk(ua.z, uc.x);
            const u64 C02 = pk(uc.y, uc.w);
            const u64 U11 = pk(ua.y, ua.y);
            const u64 U00 = pk(ua.x, ua.x);

            u64 w02 = fma2(ecK02, C02, neeK02);
            w02 = fma2(ehK02, H02, w02);
            w02 = fma2(esK02, U11, w02);
            const u64 eu02 = mul2(eeK02, U00);
            const u64 q02  = fma2(eu02, I02, w02);

            const float d12 = i0 - i1;
            const float d23 = i1 - i2;
            const u64 D   = pk(d12, d23);
            const u64 X11 = pk(x1, x1);
            const u64 t02 = mul2(G02, D);
            const u64 m02 = fma2(t02, X11, q02);
            float m0, m2; upk(m0, m2, m02);

            const float w1 = fmaf(esK1, ua.y, fmaf(ehK1, ua.w, fmaf(ecK1, uc.z, neeK1)));
            const float q1 = fmaf(eeK1 * ua.x, i1, w1);
            const float m1 = fmaf(g23_1 * d23, x2, fmaf(ng12_1 * d12, x0, q1));

            u64 r02 = fma2(P3P3, m02, P2P2);
            r02 = fma2(r02, m02, P1P1);
            r02 = fma2(r02, m02, ONE2);
            const float r1 = fmaf(fmaf(fmaf(-0.05550410866f, m1, 0.24022650696f), m1, -0.69314718056f), m1, 1.0f);

            X02 = mul2(X02, pk(ex2a(m0), ex2a(m2)));
            x1 *= ex2a(m1);
            I02 = mul2(I02, r02);
            i1 *= r1;
            upk(x0, x2, X02);
            upk(i0, i2, I02);

            ua = na; uc = nc;

            // flush 4 buffered steps: 3x STS.128 into compact ob row
            if ((j & 3) == 3) {
                float* dst = orow + (j - 3) * 3;
                *(float4*)(dst + 0) = make_float4(sb[0], sb[1], sb[2],  sb[3]);
                *(float4*)(dst + 4) = make_float4(sb[4], sb[5], sb[6],  sb[7]);
                *(float4*)(dst + 8) = make_float4(sb[8], sb[9], sb[10], sb[11]);
            }
        }

        __syncwarp();            // all lanes' STS + LDS of slot done

        if (lane == 0) {
            fence_async();       // order STS before async-proxy store
            tma_st2d(&om, c * 48, b0, obS + bo * OBUF_BYTES);
            tma_commit();
            if (c + 3 < NCHUNK) {
                mbar_expect(mb + s * 8, USLOT_BYTES);
#pragma unroll
                for (int k = 0; k < 4; k++)
                    tma_ld2d(ubS + s * USLOT_BYTES + k * 4096, &um,
                             (c + 3) * 128 + k * 32, b0, mb + s * 8);
            }
            tma_wait_read1();    // <=1 outstanding store: ob[bo^1] free
        }
        __syncwarp();
    }

    if (lane == 0) tma_wait0();  // flush final store before exit
    __syncwarp();
}

extern "C" void kernel_launch(void* const* d_in, const int* in_sizes, int n_in,
                              void* d_out, int out_size)
{
    const float* x0  = nullptr;
    const float* u   = nullptr;
    const float* lam = nullptr;
    for (int i = 0; i < n_in; i++) {
        if (in_sizes[i] == 14)               lam = (const float*)d_in[i];
        else if (in_sizes[i] == BATCH * 3)   x0  = (const float*)d_in[i];
        else                                 u   = (const float*)d_in[i];
    }

    // Resolve cuTensorMapEncodeTiled via cudart (no -lcuda link needed).
    typedef CUresult (*EncodeFn)(
        CUtensorMap*, CUtensorMapDataType, cuuint32_t, void*,
        const cuuint64_t*, const cuuint64_t*, const cuuint32_t*,
        const cuuint32_t*, CUtensorMapInterleave, CUtensorMapSwizzle,
        CUtensorMapL2promotion, CUtensorMapFloatOOBfill);
    EncodeFn encode = nullptr;
    cudaDriverEntryPointQueryResult qr;
    cudaGetDriverEntryPoint("cuTensorMapEncodeTiled", (void**)&encode,
                            cudaEnableDefault, &qr);

    // u: [8192 floats per chain, 8192 chains], row stride 32768B,
    //    box 32x32 floats (128B inner = SW128 limit), SW128.
    CUtensorMap um{};
    {
        cuuint64_t dims[2]    = {USTRIDE, BATCH};
        cuuint64_t strides[1] = {USTRIDE * 4};
        cuuint32_t box[2]     = {32, 32};
        cuuint32_t es[2]      = {1, 1};
        encode(&um, CU_TENSOR_MAP_DATA_TYPE_FLOAT32, 2, (void*)u,
               dims, strides, box, es,
               CU_TENSOR_MAP_INTERLEAVE_NONE, CU_TENSOR_MAP_SWIZZLE_128B,
               CU_TENSOR_MAP_L2_PROMOTION_L2_128B,
               CU_TENSOR_MAP_FLOAT_OOB_FILL_NONE);
    }
    // out: [3072 floats per chain, 8192 chains], row stride 12288B,
    //      box 48x32 floats, no swizzle (compact 192B smem rows).
    CUtensorMap om{};
    {
        cuuint64_t dims[2]    = {OSTRIDE, BATCH};
        cuuint64_t strides[1] = {OSTRIDE * 4};
        cuuint32_t box[2]     = {48, 32};
        cuuint32_t es[2]      = {1, 1};
        encode(&om, CU_TENSOR_MAP_DATA_TYPE_FLOAT32, 2, (void*)d_out,
               dims, strides, box, es,
               CU_TENSOR_MAP_INTERLEAVE_NONE, CU_TENSOR_MAP_SWIZZLE_NONE,
               CU_TENSOR_MAP_L2_PROMOTION_L2_128B,
               CU_TENSOR_MAP_FLOAT_OOB_FILL_NONE);
    }

    cudaFuncSetAttribute(bm_kernel,
                         cudaFuncAttributeMaxDynamicSharedMemorySize,
                         SMEM_BYTES);
    bm_kernel<<<BATCH / 64, 64, SMEM_BYTES>>>(x0, lam, um, om);
}